// round 4
// baseline (speedup 1.0000x reference)
#include <cuda_runtime.h>
#include <cstdint>
#include <cstddef>

#define NDROP 33554432u

// ---------------- device scratch (static, no runtime alloc) ----------------
__device__ float g_X[(size_t)64 * 1024 * 512];          // dropout-applied embeddings [b][l][d]
__device__ float g_preF[(size_t)1024 * 64 * 2048];      // x@Wf[:512]+bf, time-major [t][b][g]
__device__ float g_preB[(size_t)1024 * 64 * 2048];      // x@Wb[:512]+bb
__device__ unsigned char g_zb[(size_t)2 * 1024 * 32768];// zoneout bits: bit0=keep h, bit1=keep c
__device__ uint2 g_kz[2 * 1024];                        // per-step zoneout keys (fwd, bwd)
__device__ uint2 g_kd;                                  // dropout key
__device__ float g_h[2][2][64 * 512];                   // [dir][parity][b*512+d]
__device__ unsigned int g_ctr[2];                       // per-direction step barrier

// ---------------- JAX threefry2x32 (bit-exact, 20 rounds) ----------------
__device__ __forceinline__ uint32_t rotl32(uint32_t x, int r) { return (x << r) | (x >> (32 - r)); }

__device__ __forceinline__ void tf2x32(uint32_t k0, uint32_t k1, uint32_t& x0, uint32_t& x1) {
    uint32_t k2 = k0 ^ k1 ^ 0x1BD11BDAu;
    x0 += k0; x1 += k1;
#define TFR(r) { x0 += x1; x1 = rotl32(x1, r); x1 ^= x0; }
    TFR(13) TFR(15) TFR(26) TFR(6)   x0 += k1; x1 += k2 + 1u;
    TFR(17) TFR(29) TFR(16) TFR(24)  x0 += k2; x1 += k0 + 2u;
    TFR(13) TFR(15) TFR(26) TFR(6)   x0 += k0; x1 += k1 + 3u;
    TFR(17) TFR(29) TFR(16) TFR(24)  x0 += k1; x1 += k2 + 4u;
    TFR(13) TFR(15) TFR(26) TFR(6)   x0 += k2; x1 += k0 + 5u;
#undef TFR
}

// partitionable random_bits (32-bit): element i -> tf(key, (0, i)), bits = x0 ^ x1
__device__ __forceinline__ uint32_t pbits(uint32_t k0, uint32_t k1, uint32_t i) {
    uint32_t x0 = 0u, x1 = i;
    tf2x32(k0, k1, x0, x1);
    return x0 ^ x1;
}

__device__ __forceinline__ float u01(uint32_t bits) {
    return __uint_as_float((bits >> 9) | 0x3f800000u) - 1.0f;
}
__device__ __forceinline__ float sigm(float x) { return 1.0f / (1.0f + expf(-x)); }

// ---------------- K1: key derivation (fold-like split) + barrier reset ----------------
__global__ void rng_setup_kernel() {
    int tid = threadIdx.x;
    __shared__ uint32_t s[4];
    if (tid == 0) {
        g_ctr[0] = 0u; g_ctr[1] = 0u;
        // split(key(42), 3) fold-like: key_i = tf((0,42), (0, i))
        uint32_t a, b;
        a = 0u; b = 0u; tf2x32(0u, 42u, a, b); g_kd = make_uint2(a, b);
        a = 0u; b = 1u; tf2x32(0u, 42u, a, b); s[0] = a; s[1] = b;   // kf
        a = 0u; b = 2u; tf2x32(0u, 42u, a, b); s[2] = a; s[3] = b;   // kb
    }
    __syncthreads();
    if (tid < 2) {
        uint32_t k0 = s[tid * 2], k1 = s[tid * 2 + 1];
        for (int t = 0; t < 1024; ++t) {
            // split(k, 2) fold-like: kz = tf(k,(0,0)), knext = tf(k,(0,1))
            uint32_t z0 = 0u, z1 = 0u; tf2x32(k0, k1, z0, z1);
            uint32_t n0 = 0u, n1 = 1u; tf2x32(k0, k1, n0, n1);
            g_kz[tid * 1024 + t] = make_uint2(z0, z1);
            k0 = n0; k1 = n1;
        }
    }
}

// ---------------- K2: embedding gather + dropout ----------------
__global__ void embed_dropout_kernel(const int* __restrict__ tokens,
                                     const float* __restrict__ embed) {
    unsigned i = blockIdx.x * 256u + threadIdx.x;      // [0, NDROP)
    uint2 kd = g_kd;
    uint32_t bits = pbits(kd.x, kd.y, i);
    unsigned d = i & 511u, bl = i >> 9;
    float e = embed[(size_t)tokens[bl] * 512 + d];
    g_X[i] = (u01(bits) < 0.9f) ? e / 0.9f : 0.0f;
}

// ---------------- K3: zoneout mask precompute ----------------
// zm shape (2, 64, 512): h-mask at flat j = b*512+d, c-mask at j + 32768
__global__ void zoneout_kernel() {
    size_t gi = (size_t)blockIdx.x * 256 + threadIdx.x;    // [0, 2*1024*32768)
    unsigned pair = (unsigned)(gi & 32767u);
    unsigned st = (unsigned)(gi >> 15);                    // dir*1024 + s
    uint2 k = g_kz[st];
    uint32_t bh = pbits(k.x, k.y, pair);
    uint32_t bc = pbits(k.x, k.y, pair + 32768u);
    g_zb[gi] = (unsigned char)(((u01(bh) < 0.1f) ? 1u : 0u) | ((u01(bc) < 0.1f) ? 2u : 0u));
}

// ---------------- K4: input projection GEMM: pre[t][b][g] = X[b][t]@W[:512] + bias ----------------
__global__ void __launch_bounds__(256) proj_kernel(const float* __restrict__ W,
                                                   const float* __restrict__ bias,
                                                   int dir) {
    __shared__ float sA[32][68];   // [k][b], padded
    __shared__ float sB[32][64];   // [k][col]
    float* outp = dir ? g_preB : g_preF;
    int t = blockIdx.y;
    int c0 = blockIdx.x * 64;
    int tid = threadIdx.x;
    int tx = tid & 15, ty = tid >> 4;
    int lrow = tid >> 2, lk8 = (tid & 3) * 8;     // A loader
    int lkb = tid >> 3, lc8 = (tid & 7) * 8;      // B loader
    float acc[4][4] = {};

#pragma unroll 1
    for (int kt = 0; kt < 16; ++kt) {
        int k0 = kt * 32;
        const float* Xr = &g_X[(((size_t)lrow << 10) + t) * 512 + k0 + lk8];
        float4 v0 = *(const float4*)Xr;
        float4 v1 = *(const float4*)(Xr + 4);
        sA[lk8 + 0][lrow] = v0.x; sA[lk8 + 1][lrow] = v0.y;
        sA[lk8 + 2][lrow] = v0.z; sA[lk8 + 3][lrow] = v0.w;
        sA[lk8 + 4][lrow] = v1.x; sA[lk8 + 5][lrow] = v1.y;
        sA[lk8 + 6][lrow] = v1.z; sA[lk8 + 7][lrow] = v1.w;
        const float* Wr = &W[(size_t)(k0 + lkb) * 2048 + c0 + lc8];
        *(float4*)&sB[lkb][lc8]     = *(const float4*)Wr;
        *(float4*)&sB[lkb][lc8 + 4] = *(const float4*)(Wr + 4);
        __syncthreads();
#pragma unroll
        for (int k = 0; k < 32; ++k) {
            float4 a4 = *(float4*)&sA[k][ty * 4];
            float4 b4 = *(float4*)&sB[k][tx * 4];
            float av[4] = {a4.x, a4.y, a4.z, a4.w};
            float bv[4] = {b4.x, b4.y, b4.z, b4.w};
#pragma unroll
            for (int i = 0; i < 4; ++i)
#pragma unroll
                for (int j = 0; j < 4; ++j)
                    acc[i][j] = fmaf(av[i], bv[j], acc[i][j]);
        }
        __syncthreads();
    }
    float4 b4 = *(const float4*)&bias[c0 + tx * 4];
    float bv[4] = {b4.x, b4.y, b4.z, b4.w};
#pragma unroll
    for (int i = 0; i < 4; ++i) {
        int r = t * 64 + ty * 4 + i;
        float4 o;
        o.x = acc[i][0] + bv[0]; o.y = acc[i][1] + bv[1];
        o.z = acc[i][2] + bv[2]; o.w = acc[i][3] + bv[3];
        *(float4*)&outp[(size_t)r * 2048 + c0 + tx * 4] = o;
    }
}

// ---------------- K5: persistent bidirectional LSTM scan ----------------
// 128 CTAs: dir = blk>>6, cta = blk&63 owns d in [cta*8, cta*8+8).
#define SH_STRIDE 516
#define SCAN_SMEM ((32 * 512 + 64 * SH_STRIDE) * 4)

__global__ void __launch_bounds__(256, 1) scan_kernel(const int* __restrict__ lengths,
                                                      const float* __restrict__ Wf,
                                                      const float* __restrict__ Wb,
                                                      float* __restrict__ out) {
    extern __shared__ float smem[];
    float* sWT = smem;                 // 32*512
    float* sH = smem + 32 * 512;       // 64*516
    __shared__ int sLen[64];

    int dir = blockIdx.x >> 6, cta = blockIdx.x & 63, d0 = cta * 8;
    int tid = threadIdx.x;
    const float* W = dir ? Wb : Wf;

    for (int idx = tid; idx < 32 * 512; idx += 256) {
        int j = idx >> 9, k = idx & 511;
        sWT[idx] = W[(size_t)(512 + k) * 2048 + ((j >> 3) << 9) + d0 + (j & 7)];
    }
    if (tid < 64) sLen[tid] = lengths[tid];

    int q = tid >> 6, b = tid & 63;
    int dd = q * 2, d = d0 + dd;
    float c0r = 0.f, c1r = 0.f;
    volatile unsigned int* ctr = &g_ctr[dir];
    const float* pre = dir ? g_preB : g_preF;
    const unsigned char* zbase = &g_zb[(size_t)dir * 1024 * 32768];
    __syncthreads();

    for (int s = 0; s < 1024; ++s) {
        int tx = dir ? (1023 - s) : s;
        // ---- stage h (with bwd ResetCore) ----
        if (s == 0) {
            for (int i = tid * 4; i < 32768; i += 1024)
                *(float4*)&sH[(i >> 9) * SH_STRIDE + (i & 511)] = make_float4(0, 0, 0, 0);
        } else {
            const float* hg = g_h[dir][s & 1];
            for (int i = tid * 4; i < 32768; i += 1024) {
                int hb = i >> 9, hd = i & 511;
                float4 v = __ldcg((const float4*)&hg[i]);
                if (dir && (1023 - s) < sLen[hb] - 1) v = make_float4(0, 0, 0, 0);
                *(float4*)&sH[hb * SH_STRIDE + hd] = v;
            }
        }
        __syncthreads();

        // ---- prefetch x-projection + zoneout bits ----
        size_t prow = ((size_t)tx * 64 + b) * 2048 + (size_t)d;
        float2 pxi = *(const float2*)&pre[prow];
        float2 pxg = *(const float2*)&pre[prow + 512];
        float2 pxf = *(const float2*)&pre[prow + 1024];
        float2 pxo = *(const float2*)&pre[prow + 1536];
        const unsigned char* zp = &zbase[((size_t)s << 15) + b * 512 + d];
        unsigned char z0 = zp[0], z1 = zp[1];

        // ---- h @ W_h slice: 8 gate pre-activations ----
        float acc[8] = {};
        const float* hrow = &sH[b * SH_STRIDE];
#pragma unroll 2
        for (int k = 0; k < 512; k += 4) {
            float4 hv = *(const float4*)&hrow[k];
#pragma unroll
            for (int u = 0; u < 8; ++u) {
                const float4 w = *(const float4*)&sWT[((u >> 1) * 8 + dd + (u & 1)) * 512 + k];
                acc[u] = fmaf(hv.x, w.x, fmaf(hv.y, w.y, fmaf(hv.z, w.z, fmaf(hv.w, w.w, acc[u]))));
            }
        }

        // ---- gates + zoneout ----
        if (dir && (1023 - s) < sLen[b] - 1) { c0r = 0.f; c1r = 0.f; }
        float i0 = pxi.x + acc[0], i1 = pxi.y + acc[1];
        float gg0 = pxg.x + acc[2], gg1 = pxg.y + acc[3];
        float f0 = sigm(pxf.x + acc[4] + 1.f), f1 = sigm(pxf.y + acc[5] + 1.f);
        float o0 = sigm(pxo.x + acc[6]), o1 = sigm(pxo.y + acc[7]);
        float cn0 = f0 * c0r + sigm(i0) * tanhf(gg0);
        float cn1 = f1 * c1r + sigm(i1) * tanhf(gg1);
        float hn0 = o0 * tanhf(cn0);
        float hn1 = o1 * tanhf(cn1);
        float hp0 = hrow[d], hp1 = hrow[d + 1];
        float ho0 = (z0 & 1) ? hp0 : hn0;
        float ho1 = (z1 & 1) ? hp1 : hn1;
        c0r = (z0 & 2) ? c0r : cn0;
        c1r = (z1 & 2) ? c1r : cn1;

        // ---- write h (for next step) + output ----
        float* hw = g_h[dir][(s + 1) & 1];
        float2 hv2 = make_float2(ho0, ho1);
        __stcg((float2*)&hw[b * 512 + d], hv2);
        *(float2*)&out[(((size_t)b << 10) + tx) * 1024 + ((size_t)dir << 9) + d] = hv2;

        // ---- per-direction grid barrier ----
        __syncthreads();
        if (s < 1023) {
            if (tid == 0) {
                __threadfence();
                atomicAdd((unsigned int*)ctr, 1u);
                unsigned int target = 64u * (unsigned)(s + 1);
                while (*ctr < target) __nanosleep(64);
                __threadfence();
            }
            __syncthreads();
        }
    }
}

// ---------------- launch ----------------
extern "C" void kernel_launch(void* const* d_in, const int* in_sizes, int n_in,
                              void* d_out, int out_size) {
    (void)in_sizes; (void)n_in; (void)out_size;
    const int*   tokens  = (const int*)d_in[0];
    const int*   lengths = (const int*)d_in[1];
    const float* embed   = (const float*)d_in[2];
    const float* Wf      = (const float*)d_in[3];
    const float* bf      = (const float*)d_in[4];
    const float* Wb      = (const float*)d_in[5];
    const float* bb      = (const float*)d_in[6];
    float* out = (float*)d_out;

    cudaFuncSetAttribute(scan_kernel, cudaFuncAttributeMaxDynamicSharedMemorySize, SCAN_SMEM);

    rng_setup_kernel<<<1, 64>>>();
    embed_dropout_kernel<<<NDROP / 256, 256>>>(tokens, embed);
    zoneout_kernel<<<(2u * 1024u * 32768u) / 256u, 256>>>();
    dim3 pg(32, 1024);
    proj_kernel<<<pg, 256>>>(Wf, bf, 0);
    proj_kernel<<<pg, 256>>>(Wb, bb, 1);
    scan_kernel<<<128, 256, SCAN_SMEM>>>(lengths, Wf, Wb, out);
}